// round 15
// baseline (speedup 1.0000x reference)
#include <cuda_runtime.h>

// Problem constants (fixed by the dataset shapes)
#define B_   32
#define NL_  13
#define L_   1024
#define D_   768
#define LCHUNKS_ 32
#define LCHUNK_  (L_ / LCHUNKS_)   // 32 rows per block

// Scratch (no allocation allowed): per-(batch,pos) weights + per-batch lengths.
__device__ float g_w[B_ * L_];
__device__ int   g_len[B_];

// ---------------------------------------------------------------------------
// Kernel 1: per-batch run-length weights + zero the output + publish lengths.
// EXACT R9 version (proven). One block per batch, L_ threads, shuffle scan.
// Ends with griddepcontrol.launch_dependents (PDL producer side).
//
// Integer inputs are read through an int32 view with runtime-detected element
// stride (JAX silently downcasts int64->int32 without x64). lengths are in
// [512,1024] (never 0), so word[1]==0  <=>  little-endian int64 layout.
// vq values < 320 < 2^31, so low words fully determine equality either way.
// ---------------------------------------------------------------------------
__global__ void __launch_bounds__(L_, 1)
vq_weights_kernel(const int* __restrict__ len32,
                  const int* __restrict__ vq32,
                  float* __restrict__ out)
{
    const int b    = blockIdx.x;
    const int i    = threadIdx.x;
    const int lane = i & 31;
    const int warp = i >> 5;

    __shared__ int s_rl[L_];        // run length per segment id
    __shared__ int s_v0[L_];        // staged vq low words (component 0)
    __shared__ int s_v1[L_];        // staged vq low words (component 1)
    __shared__ int s_wsum[32];      // per-warp scan totals

    // Zero the output slice for this batch (d_out is poisoned to 0xAA).
    if (i < D_) out[b * D_ + i] = 0.0f;

    // dtype detection (uniform)
    const int stride = (len32[1] == 0) ? 2 : 1;

    const int  len   = len32[b * stride];
    const bool valid = i < len;
    if (i == 0) g_len[b] = len;

    const int ebase = (b * L_ + i) * 2;
    int v0 = vq32[(ebase + 0) * stride];
    int v1 = vq32[(ebase + 1) * stride];
    s_v0[i] = v0;
    s_v1[i] = v1;
    s_rl[i] = 0;
    __syncthreads();

    // boundary flag
    bool bnd;
    if (i == 0) bnd = valid;
    else        bnd = valid && (v0 != s_v0[i - 1] || v1 != s_v1[i - 1]);

    // warp-level inclusive scan of flags
    int scan = bnd ? 1 : 0;
    #pragma unroll
    for (int off = 1; off < 32; off <<= 1) {
        int n = __shfl_up_sync(0xffffffffu, scan, off);
        if (lane >= off) scan += n;
    }
    if (lane == 31) s_wsum[warp] = scan;
    __syncthreads();

    if (warp == 0) {
        int v = s_wsum[lane];
        #pragma unroll
        for (int off = 1; off < 32; off <<= 1) {
            int n = __shfl_up_sync(0xffffffffu, v, off);
            if (lane >= off) v += n;
        }
        s_wsum[lane] = v;
    }
    __syncthreads();

    const int incl  = scan + (warp > 0 ? s_wsum[warp - 1] : 0);  // inclusive cumsum
    const int total = s_wsum[31];                                 // num_runs

    int seg = incl - 1;
    seg = max(0, min(seg, L_ - 1));

    if (valid) atomicAdd(&s_rl[seg], 1);
    __syncthreads();

    float wv = 0.0f;
    if (valid) {
        float rl = (float)max(s_rl[seg], 1);
        wv = 1.0f / ((float)total * rl);
    }
    g_w[b * L_ + i] = wv;

    // All of this block's global writes are done -> allow dependent launch.
    __syncthreads();
    asm volatile("griddepcontrol.launch_dependents;");
}

// ---------------------------------------------------------------------------
// Kernel 2: weighted pool over the LAST layer of input_feature.
// Loop body is the EXACT R9 body (proven best, 12.768us) -- untouched.
// New, schedule-neutral pre-wait work only:
//   (a) dead-block exit straight from the INPUT len32 (no producer dep);
//   (b) prefetch.global.L2 of this block's whole 96KB chunk: 4 prefetches
//       per thread (192 x 4 = 768 lines = 32 rows x 24 lines/row), no
//       destination registers, no dependency chains -> the loop schedule is
//       unchanged while ~DRAM-rate bytes flow into L2 during the producer's
//       ~1.8us drain.
// Epilogue: one red.global.v4.f32.
// ---------------------------------------------------------------------------
__global__ void __launch_bounds__(D_ / 4, 8)
vq_pool_kernel(const float* __restrict__ feat,
               const int*   __restrict__ len32,
               float* __restrict__ out)
{
    const int b  = blockIdx.y;
    const int lc = blockIdx.x;
    const int t  = threadIdx.x;     // 0..191

    const int l0 = lc * LCHUNK_;

    // (a) dead-block exit from INPUT data -- no producer dependence.
    const int stride = (len32[1] == 0) ? 2 : 1;
    if (l0 >= len32[b * stride]) return;

    const float4* __restrict__ fb = (const float4*)
        (feat + ((size_t)b * NL_ + (NL_ - 1)) * (size_t)(L_ * D_));
    const float4* __restrict__ wb4 = (const float4*)(g_w + b * L_);
    float* ob = out + b * D_ + t * 4;

    // (b) L2 prefetch of the full chunk: thread t covers 128B line (t%24) of
    // rows t/24, t/24+8, t/24+16, t/24+24 (24 lines/row x 8 row-groups).
    {
        const char* cbase = (const char*)fb + (size_t)l0 * (D_ * 4)
                          + (t % 24) * 128 + (t / 24) * (D_ * 4);
        #pragma unroll
        for (int k = 0; k < 4; ++k)
            asm volatile("prefetch.global.L2 [%0];"
                         :: "l"(cbase + (size_t)k * 8 * (D_ * 4)));
    }

    // Wait for the producer kernel's writes (g_w, zeroed out).
    asm volatile("griddepcontrol.wait;" ::: "memory");

    // ---- EXACT R9 streaming body ----
    float4 acc = make_float4(0.f, 0.f, 0.f, 0.f);

    #pragma unroll
    for (int j = 0; j < LCHUNK_; j += 8) {
        const float4 w0 = wb4[(l0 + j) / 4 + 0];   // weights l0+j .. l0+j+3
        const float4 w1 = wb4[(l0 + j) / 4 + 1];   // weights l0+j+4 .. l0+j+7
        const float wl[8] = { w0.x, w0.y, w0.z, w0.w, w1.x, w1.y, w1.z, w1.w };

        float4 f[8];
        #pragma unroll
        for (int k = 0; k < 8; ++k)
            f[k] = __ldcs(&fb[(size_t)(l0 + j + k) * (D_ / 4) + t]);
        #pragma unroll
        for (int k = 0; k < 8; ++k) {
            acc.x = fmaf(wl[k], f[k].x, acc.x);
            acc.y = fmaf(wl[k], f[k].y, acc.y);
            acc.z = fmaf(wl[k], f[k].z, acc.z);
            acc.w = fmaf(wl[k], f[k].w, acc.w);
        }
    }

    // Single vectorized reduction (16B-aligned)
    asm volatile("red.global.add.v4.f32 [%0], {%1, %2, %3, %4};"
                 :: "l"(ob), "f"(acc.x), "f"(acc.y), "f"(acc.z), "f"(acc.w)
                 : "memory");
}

// ---------------------------------------------------------------------------
extern "C" void kernel_launch(void* const* d_in, const int* in_sizes, int n_in,
                              void* d_out, int out_size)
{
    const float* feat  = (const float*)d_in[0];   // (B, NL, L, D) f32
    const int*   len32 = (const int*)d_in[1];     // (B,) i32 or i64 (detected)
    const int*   vq32  = (const int*)d_in[2];     // (B, L, 2) i32 or i64 (detected)
    float*       out   = (float*)d_out;           // (B, D) f32

    vq_weights_kernel<<<B_, L_>>>(len32, vq32, out);

    // Pool kernel with programmatic stream serialization (PDL).
    cudaLaunchConfig_t cfg = {};
    cfg.gridDim  = dim3(LCHUNKS_, B_);
    cfg.blockDim = dim3(D_ / 4);
    cudaLaunchAttribute attr[1];
    attr[0].id = cudaLaunchAttributeProgrammaticStreamSerialization;
    attr[0].val.programmaticStreamSerializationAllowed = 1;
    cfg.attrs    = attr;
    cfg.numAttrs = 1;
    cudaLaunchKernelEx(&cfg, vq_pool_kernel, feat, len32, out);
}

// round 16
// speedup vs baseline: 1.1800x; 1.1800x over previous
#include <cuda_runtime.h>

// Problem constants (fixed by the dataset shapes)
#define B_   32
#define NL_  13
#define L_   1024
#define D_   768
#define LCHUNKS_ 32
#define LCHUNK_  (L_ / LCHUNKS_)   // 32 rows per block

// Scratch (no allocation allowed): per-(batch,pos) weights + per-batch lengths.
__device__ float g_w[B_ * L_];
__device__ int   g_len[B_];

// ---------------------------------------------------------------------------
// Kernel 1: per-batch run-length weights + zero the output + publish lengths.
// One block per batch, L_ threads. R9 structure, but the intra-warp inclusive
// scan uses ballot+popc (1 ballot + 1 popc, ~8cyc) instead of a 5-step shuffle
// scan (~45cyc dependent chain); warp total = popc(ballot).
// Ends with griddepcontrol.launch_dependents (PDL producer side).
//
// Integer inputs are read through an int32 view with runtime-detected element
// stride (JAX silently downcasts int64->int32 without x64). lengths are in
// [512,1024] (never 0), so word[1]==0  <=>  little-endian int64 layout.
// vq values < 320 < 2^31, so low words fully determine equality either way.
// ---------------------------------------------------------------------------
__global__ void __launch_bounds__(L_, 1)
vq_weights_kernel(const int* __restrict__ len32,
                  const int* __restrict__ vq32,
                  float* __restrict__ out)
{
    const int b    = blockIdx.x;
    const int i    = threadIdx.x;
    const int lane = i & 31;
    const int warp = i >> 5;

    __shared__ int s_rl[L_];        // run length per segment id
    __shared__ int s_v0[L_];        // staged vq low words (component 0)
    __shared__ int s_v1[L_];        // staged vq low words (component 1)
    __shared__ int s_wsum[32];      // per-warp totals -> scanned

    // Zero the output slice for this batch (d_out is poisoned to 0xAA).
    if (i < D_) out[b * D_ + i] = 0.0f;

    // dtype detection (uniform)
    const int stride = (len32[1] == 0) ? 2 : 1;

    const int  len   = len32[b * stride];
    const bool valid = i < len;
    if (i == 0) g_len[b] = len;

    const int ebase = (b * L_ + i) * 2;
    int v0 = vq32[(ebase + 0) * stride];
    int v1 = vq32[(ebase + 1) * stride];
    s_v0[i] = v0;
    s_v1[i] = v1;
    s_rl[i] = 0;
    __syncthreads();

    // boundary flag
    bool bnd;
    if (i == 0) bnd = valid;
    else        bnd = valid && (v0 != s_v0[i - 1] || v1 != s_v1[i - 1]);

    // intra-warp inclusive scan of flags via ballot+popc (replaces 5-step shfl scan)
    const unsigned bmask = __ballot_sync(0xffffffffu, bnd);
    const int scan = __popc(bmask & (0xffffffffu >> (31 - lane)));  // lanemask_le
    if (lane == 0) s_wsum[warp] = __popc(bmask);                    // warp total
    __syncthreads();

    if (warp == 0) {
        int v = s_wsum[lane];
        #pragma unroll
        for (int off = 1; off < 32; off <<= 1) {
            int n = __shfl_up_sync(0xffffffffu, v, off);
            if (lane >= off) v += n;
        }
        s_wsum[lane] = v;
    }
    __syncthreads();

    const int incl  = scan + (warp > 0 ? s_wsum[warp - 1] : 0);  // inclusive cumsum
    const int total = s_wsum[31];                                 // num_runs

    int seg = incl - 1;
    seg = max(0, min(seg, L_ - 1));

    if (valid) atomicAdd(&s_rl[seg], 1);
    __syncthreads();

    float wv = 0.0f;
    if (valid) {
        float rl = (float)max(s_rl[seg], 1);
        wv = 1.0f / ((float)total * rl);
    }
    g_w[b * L_ + i] = wv;

    // All of this block's global writes are done -> allow dependent launch.
    __syncthreads();
    asm volatile("griddepcontrol.launch_dependents;");
}

// ---------------------------------------------------------------------------
// Kernel 2: weighted pool over the LAST layer of input_feature.
// EXACT R9 kernel (proven best, 12.768us) -- FROZEN. grid (32, 32) = 1024
// blocks (one wave at 8 blocks/SM), 192 threads (one float4 column group per
// thread). Static fully-unrolled 32-row chunk, 8-deep batched __ldcs LDG.128,
// weights as 2x float4 per batch of 8 rows (block-uniform, L1 broadcast).
// PDL: prologue before griddepcontrol.wait. Epilogue: one red.global.v4.f32.
// ---------------------------------------------------------------------------
__global__ void __launch_bounds__(D_ / 4, 8)
vq_pool_kernel(const float* __restrict__ feat, float* __restrict__ out)
{
    const int b  = blockIdx.y;
    const int lc = blockIdx.x;
    const int t  = threadIdx.x;     // 0..191

    const int l0 = lc * LCHUNK_;

    // Prologue independent of kernel 1's results.
    const float4* __restrict__ fb = (const float4*)
        (feat + ((size_t)b * NL_ + (NL_ - 1)) * (size_t)(L_ * D_));
    const float4* __restrict__ wb4 = (const float4*)(g_w + b * L_);
    float* ob = out + b * D_ + t * 4;

    // Wait for the producer kernel's writes (g_len, g_w, zeroed out).
    asm volatile("griddepcontrol.wait;" ::: "memory");

    if (l0 >= g_len[b]) return;     // whole chunk is zero-weight

    float4 acc = make_float4(0.f, 0.f, 0.f, 0.f);

    #pragma unroll
    for (int j = 0; j < LCHUNK_; j += 8) {
        const float4 w0 = wb4[(l0 + j) / 4 + 0];   // weights l0+j .. l0+j+3
        const float4 w1 = wb4[(l0 + j) / 4 + 1];   // weights l0+j+4 .. l0+j+7
        const float wl[8] = { w0.x, w0.y, w0.z, w0.w, w1.x, w1.y, w1.z, w1.w };

        float4 f[8];
        #pragma unroll
        for (int k = 0; k < 8; ++k)
            f[k] = __ldcs(&fb[(size_t)(l0 + j + k) * (D_ / 4) + t]);
        #pragma unroll
        for (int k = 0; k < 8; ++k) {
            acc.x = fmaf(wl[k], f[k].x, acc.x);
            acc.y = fmaf(wl[k], f[k].y, acc.y);
            acc.z = fmaf(wl[k], f[k].z, acc.z);
            acc.w = fmaf(wl[k], f[k].w, acc.w);
        }
    }

    // Single vectorized reduction (16B-aligned)
    asm volatile("red.global.add.v4.f32 [%0], {%1, %2, %3, %4};"
                 :: "l"(ob), "f"(acc.x), "f"(acc.y), "f"(acc.z), "f"(acc.w)
                 : "memory");
}

// ---------------------------------------------------------------------------
extern "C" void kernel_launch(void* const* d_in, const int* in_sizes, int n_in,
                              void* d_out, int out_size)
{
    const float* feat  = (const float*)d_in[0];   // (B, NL, L, D) f32
    const int*   len32 = (const int*)d_in[1];     // (B,) i32 or i64 (detected)
    const int*   vq32  = (const int*)d_in[2];     // (B, L, 2) i32 or i64 (detected)
    float*       out   = (float*)d_out;           // (B, D) f32

    vq_weights_kernel<<<B_, L_>>>(len32, vq32, out);

    // Pool kernel with programmatic stream serialization (PDL).
    cudaLaunchConfig_t cfg = {};
    cfg.gridDim  = dim3(LCHUNKS_, B_);
    cfg.blockDim = dim3(D_ / 4);
    cudaLaunchAttribute attr[1];
    attr[0].id = cudaLaunchAttributeProgrammaticStreamSerialization;
    attr[0].val.programmaticStreamSerializationAllowed = 1;
    cfg.attrs    = attr;
    cfg.numAttrs = 1;
    cudaLaunchKernelEx(&cfg, vq_pool_kernel, feat, out);
}

// round 17
// speedup vs baseline: 1.1830x; 1.0025x over previous
#include <cuda_runtime.h>

// Problem constants (fixed by the dataset shapes)
#define B_   32
#define NL_  13
#define L_   1024
#define D_   768
#define LCHUNKS_ 32
#define LCHUNK_  (L_ / LCHUNKS_)   // 32 rows per block

// Scratch (no allocation allowed): per-(batch,pos) weights + per-batch lengths.
__device__ float g_w[B_ * L_];
__device__ int   g_len[B_];

// ---------------------------------------------------------------------------
// Kernel 1: per-batch run-length weights + zero the output + publish lengths.
// One block per batch, L_ threads. Ballot+popc intra-warp scan (R16).
// vq pair loaded as ONE vectorized LDG (int4 for int64 layout / int2 for
// int32 layout) instead of two stride-2 scalar loads: full sector
// utilization, one scoreboard dep on the serial critical path.
// Ends with griddepcontrol.launch_dependents (PDL producer side).
//
// Integer inputs are read through an int32 view with runtime-detected element
// stride (JAX silently downcasts int64->int32 without x64). lengths are in
// [512,1024] (never 0), so word[1]==0  <=>  little-endian int64 layout.
// vq values < 320 < 2^31, so low words fully determine equality either way.
// ---------------------------------------------------------------------------
__global__ void __launch_bounds__(L_, 1)
vq_weights_kernel(const int* __restrict__ len32,
                  const int* __restrict__ vq32,
                  float* __restrict__ out)
{
    const int b    = blockIdx.x;
    const int i    = threadIdx.x;
    const int lane = i & 31;
    const int warp = i >> 5;

    __shared__ int s_rl[L_];        // run length per segment id
    __shared__ int s_v0[L_];        // staged vq low words (component 0)
    __shared__ int s_v1[L_];        // staged vq low words (component 1)
    __shared__ int s_wsum[32];      // per-warp totals -> scanned

    // Zero the output slice for this batch (d_out is poisoned to 0xAA).
    if (i < D_) out[b * D_ + i] = 0.0f;

    // dtype detection (uniform)
    const int stride = (len32[1] == 0) ? 2 : 1;

    const int  len   = len32[b * stride];
    const bool valid = i < len;
    if (i == 0) g_len[b] = len;

    // vq pair (b, i, 0..1) via one vectorized load.
    int v0, v1;
    const int pair = b * L_ + i;    // pair index
    if (stride == 2) {
        // int64 layout: pair = 16 bytes = {v0.lo, v0.hi, v1.lo, v1.hi}
        const int4 p = ((const int4*)vq32)[pair];
        v0 = p.x; v1 = p.z;
    } else {
        // int32 layout: pair = 8 bytes = {v0, v1}
        const int2 p = ((const int2*)vq32)[pair];
        v0 = p.x; v1 = p.y;
    }
    s_v0[i] = v0;
    s_v1[i] = v1;
    s_rl[i] = 0;
    __syncthreads();

    // boundary flag
    bool bnd;
    if (i == 0) bnd = valid;
    else        bnd = valid && (v0 != s_v0[i - 1] || v1 != s_v1[i - 1]);

    // intra-warp inclusive scan of flags via ballot+popc
    const unsigned bmask = __ballot_sync(0xffffffffu, bnd);
    const int scan = __popc(bmask & (0xffffffffu >> (31 - lane)));  // lanemask_le
    if (lane == 0) s_wsum[warp] = __popc(bmask);                    // warp total
    __syncthreads();

    if (warp == 0) {
        int v = s_wsum[lane];
        #pragma unroll
        for (int off = 1; off < 32; off <<= 1) {
            int n = __shfl_up_sync(0xffffffffu, v, off);
            if (lane >= off) v += n;
        }
        s_wsum[lane] = v;
    }
    __syncthreads();

    const int incl  = scan + (warp > 0 ? s_wsum[warp - 1] : 0);  // inclusive cumsum
    const int total = s_wsum[31];                                 // num_runs

    int seg = incl - 1;
    seg = max(0, min(seg, L_ - 1));

    if (valid) atomicAdd(&s_rl[seg], 1);
    __syncthreads();

    float wv = 0.0f;
    if (valid) {
        float rl = (float)max(s_rl[seg], 1);
        wv = 1.0f / ((float)total * rl);
    }
    g_w[b * L_ + i] = wv;

    // All of this block's global writes are done -> allow dependent launch.
    __syncthreads();
    asm volatile("griddepcontrol.launch_dependents;");
}

// ---------------------------------------------------------------------------
// Kernel 2: weighted pool over the LAST layer of input_feature.
// EXACT R9 kernel (proven best, 12.768us) -- FROZEN. grid (32, 32) = 1024
// blocks (one wave at 8 blocks/SM), 192 threads (one float4 column group per
// thread). Static fully-unrolled 32-row chunk, 8-deep batched __ldcs LDG.128,
// weights as 2x float4 per batch of 8 rows (block-uniform, L1 broadcast).
// PDL: prologue before griddepcontrol.wait. Epilogue: one red.global.v4.f32.
// ---------------------------------------------------------------------------
__global__ void __launch_bounds__(D_ / 4, 8)
vq_pool_kernel(const float* __restrict__ feat, float* __restrict__ out)
{
    const int b  = blockIdx.y;
    const int lc = blockIdx.x;
    const int t  = threadIdx.x;     // 0..191

    const int l0 = lc * LCHUNK_;

    // Prologue independent of kernel 1's results.
    const float4* __restrict__ fb = (const float4*)
        (feat + ((size_t)b * NL_ + (NL_ - 1)) * (size_t)(L_ * D_));
    const float4* __restrict__ wb4 = (const float4*)(g_w + b * L_);
    float* ob = out + b * D_ + t * 4;

    // Wait for the producer kernel's writes (g_len, g_w, zeroed out).
    asm volatile("griddepcontrol.wait;" ::: "memory");

    if (l0 >= g_len[b]) return;     // whole chunk is zero-weight

    float4 acc = make_float4(0.f, 0.f, 0.f, 0.f);

    #pragma unroll
    for (int j = 0; j < LCHUNK_; j += 8) {
        const float4 w0 = wb4[(l0 + j) / 4 + 0];   // weights l0+j .. l0+j+3
        const float4 w1 = wb4[(l0 + j) / 4 + 1];   // weights l0+j+4 .. l0+j+7
        const float wl[8] = { w0.x, w0.y, w0.z, w0.w, w1.x, w1.y, w1.z, w1.w };

        float4 f[8];
        #pragma unroll
        for (int k = 0; k < 8; ++k)
            f[k] = __ldcs(&fb[(size_t)(l0 + j + k) * (D_ / 4) + t]);
        #pragma unroll
        for (int k = 0; k < 8; ++k) {
            acc.x = fmaf(wl[k], f[k].x, acc.x);
            acc.y = fmaf(wl[k], f[k].y, acc.y);
            acc.z = fmaf(wl[k], f[k].z, acc.z);
            acc.w = fmaf(wl[k], f[k].w, acc.w);
        }
    }

    // Single vectorized reduction (16B-aligned)
    asm volatile("red.global.add.v4.f32 [%0], {%1, %2, %3, %4};"
                 :: "l"(ob), "f"(acc.x), "f"(acc.y), "f"(acc.z), "f"(acc.w)
                 : "memory");
}

// ---------------------------------------------------------------------------
extern "C" void kernel_launch(void* const* d_in, const int* in_sizes, int n_in,
                              void* d_out, int out_size)
{
    const float* feat  = (const float*)d_in[0];   // (B, NL, L, D) f32
    const int*   len32 = (const int*)d_in[1];     // (B,) i32 or i64 (detected)
    const int*   vq32  = (const int*)d_in[2];     // (B, L, 2) i32 or i64 (detected)
    float*       out   = (float*)d_out;           // (B, D) f32

    vq_weights_kernel<<<B_, L_>>>(len32, vq32, out);

    // Pool kernel with programmatic stream serialization (PDL).
    cudaLaunchConfig_t cfg = {};
    cfg.gridDim  = dim3(LCHUNKS_, B_);
    cfg.blockDim = dim3(D_ / 4);
    cudaLaunchAttribute attr[1];
    attr[0].id = cudaLaunchAttributeProgrammaticStreamSerialization;
    attr[0].val.programmaticStreamSerializationAllowed = 1;
    cfg.attrs    = attr;
    cfg.numAttrs = 1;
    cudaLaunchKernelEx(&cfg, vq_pool_kernel, feat, out);
}